// round 1
// baseline (speedup 1.0000x reference)
#include <cuda_runtime.h>
#include <math.h>

#define N_NODES 50000
#define N_GRAPHS 512
#define FC 128
#define NCLS 2

// ---------------- scratch (device globals; no allocs allowed) ----------------
__device__ float g_agg[(size_t)N_NODES * FC];
__device__ float g_h1[(size_t)N_NODES * FC];
__device__ float g_h2[(size_t)N_NODES * FC];
__device__ float g_inv[N_NODES];
__device__ int   g_cnt[N_NODES];
__device__ float g_psum[N_GRAPHS * FC];
__device__ int   g_pcnt[N_GRAPHS];

// ---------------- init / degree ----------------
__global__ void zero_init_kernel() {
    int i = blockIdx.x * blockDim.x + threadIdx.x;
    if (i < N_NODES) g_cnt[i] = 0;
    if (i < N_GRAPHS * FC) g_psum[i] = 0.f;
    if (i < N_GRAPHS) g_pcnt[i] = 0;
}

__global__ void zero_agg_kernel() {
    int i = blockIdx.x * blockDim.x + threadIdx.x;  // exactly N*FC/4 threads
    float4 z = make_float4(0.f, 0.f, 0.f, 0.f);
    reinterpret_cast<float4*>(g_agg)[i] = z;
}

__global__ void degree_kernel(const int* __restrict__ ei, int E) {
    int e = blockIdx.x * blockDim.x + threadIdx.x;
    if (e < E) atomicAdd(&g_cnt[ei[E + e]], 1);
}

__global__ void make_inv_kernel() {
    int i = blockIdx.x * blockDim.x + threadIdx.x;
    if (i < N_NODES) g_inv[i] = 1.f / fmaxf((float)g_cnt[i], 1.f);
}

// ---------------- edge scatter: agg[dst] += x[src] (one warp per edge) ----------------
__global__ void scatter_kernel(const float* __restrict__ x, const int* __restrict__ ei, int E) {
    int gid = blockIdx.x * blockDim.x + threadIdx.x;
    int e = gid >> 5;
    int lane = gid & 31;
    if (e >= E) return;
    int src = __ldg(&ei[e]);
    int dst = __ldg(&ei[E + e]);
    float4 v = *reinterpret_cast<const float4*>(x + (size_t)src * FC + lane * 4);
    float* o = g_agg + (size_t)dst * FC + lane * 4;
    atomicAdd(o + 0, v.x);
    atomicAdd(o + 1, v.y);
    atomicAdd(o + 2, v.z);
    atomicAdd(o + 3, v.w);
}

// ---------------- fused layer: h = LN(relu(agg*inv @ wl + bl + xin @ wr) [+ xin]) -----
// BM=64 rows, BN=128 (full width), K = 2*128 (agg half then xin half).
// 256 threads: warp w owns rows w*8..w*8+7; lane owns cols lane*4..lane*4+3.
// LayerNorm reduces across the 32 lanes of a warp (full 128-wide row).
template <bool RESID>
__global__ void __launch_bounds__(256) sage_layer_kernel(
    const float* __restrict__ xin,
    const float* __restrict__ wl, const float* __restrict__ wr,
    const float* __restrict__ bias, const float* __restrict__ gam,
    const float* __restrict__ bet,
    float* __restrict__ hout)
{
    __shared__ float As[64][32];    // [row][k]
    __shared__ float Bs[32][128];   // [k][n]

    const int tid  = threadIdx.x;
    const int lane = tid & 31;
    const int warp = tid >> 5;
    const int row0 = blockIdx.x * 64;

    float acc[8][4];
#pragma unroll
    for (int i = 0; i < 8; i++)
#pragma unroll
        for (int j = 0; j < 4; j++) acc[i][j] = 0.f;

    const int lr = tid >> 3;        // 0..31 (A-tile row; second row at +32)
    const int lk = (tid & 7) * 4;   // A-tile k (float4)
    const int bn = (tid & 31) * 4;  // B-tile n (float4)
    const int bk = tid >> 5;        // B-tile k base (step 8)

    for (int ph = 0; ph < 8; ph++) {
        const bool aggHalf = (ph < 4);
        const float* A = aggHalf ? g_agg : xin;
        const float* B = aggHalf ? wl : wr;
        const int kt = (ph & 3) * 32;

        // load A tile (scale agg rows by 1/deg)
#pragma unroll
        for (int s = 0; s < 2; s++) {
            int r = lr + s * 32;
            int gr = row0 + r;
            float4 v = make_float4(0.f, 0.f, 0.f, 0.f);
            if (gr < N_NODES) {
                v = *reinterpret_cast<const float4*>(A + (size_t)gr * FC + kt + lk);
                if (aggHalf) {
                    float sc = g_inv[gr];
                    v.x *= sc; v.y *= sc; v.z *= sc; v.w *= sc;
                }
            }
            *reinterpret_cast<float4*>(&As[r][lk]) = v;
        }
        // load B tile
#pragma unroll
        for (int s = 0; s < 4; s++) {
            int k = bk + s * 8;
            *reinterpret_cast<float4*>(&Bs[k][bn]) =
                *reinterpret_cast<const float4*>(B + (size_t)(kt + k) * FC + bn);
        }
        __syncthreads();

#pragma unroll
        for (int k = 0; k < 32; k++) {
            float4 b4 = *reinterpret_cast<float4*>(&Bs[k][lane * 4]);
#pragma unroll
            for (int i = 0; i < 8; i++) {
                float a = As[warp * 8 + i][k];
                acc[i][0] = fmaf(a, b4.x, acc[i][0]);
                acc[i][1] = fmaf(a, b4.y, acc[i][1]);
                acc[i][2] = fmaf(a, b4.z, acc[i][2]);
                acc[i][3] = fmaf(a, b4.w, acc[i][3]);
            }
        }
        __syncthreads();
    }

    // ---------- epilogue: bias, relu, residual, LayerNorm ----------
    const int cbase = lane * 4;
    const float4 b4  = *reinterpret_cast<const float4*>(bias + cbase);
    const float4 gm4 = *reinterpret_cast<const float4*>(gam + cbase);
    const float4 be4 = *reinterpret_cast<const float4*>(bet + cbase);

#pragma unroll
    for (int i = 0; i < 8; i++) {
        int gr = row0 + warp * 8 + i;      // warp-uniform
        if (gr >= N_NODES) continue;        // uniform branch: shuffles safe
        float v0 = fmaxf(acc[i][0] + b4.x, 0.f);
        float v1 = fmaxf(acc[i][1] + b4.y, 0.f);
        float v2 = fmaxf(acc[i][2] + b4.z, 0.f);
        float v3 = fmaxf(acc[i][3] + b4.w, 0.f);
        if (RESID) {
            float4 r4 = *reinterpret_cast<const float4*>(xin + (size_t)gr * FC + cbase);
            v0 += r4.x; v1 += r4.y; v2 += r4.z; v3 += r4.w;
        }
        float s = v0 + v1 + v2 + v3;
        float q = v0 * v0 + v1 * v1 + v2 * v2 + v3 * v3;
#pragma unroll
        for (int o = 16; o > 0; o >>= 1) {
            s += __shfl_xor_sync(0xffffffffu, s, o);
            q += __shfl_xor_sync(0xffffffffu, q, o);
        }
        float mean = s * (1.f / 128.f);
        float var  = q * (1.f / 128.f) - mean * mean;
        float rs   = rsqrtf(var + 1e-5f);
        float4 o4;
        o4.x = (v0 - mean) * rs * gm4.x + be4.x;
        o4.y = (v1 - mean) * rs * gm4.y + be4.y;
        o4.z = (v2 - mean) * rs * gm4.z + be4.z;
        o4.w = (v3 - mean) * rs * gm4.w + be4.w;
        *reinterpret_cast<float4*>(hout + (size_t)gr * FC + cbase) = o4;
    }
}

// ---------------- global mean pool accumulate (one warp per node) ----------------
__global__ void pool_accum_kernel(const float* __restrict__ h, const int* __restrict__ batch) {
    int gid = blockIdx.x * blockDim.x + threadIdx.x;
    int n = gid >> 5;
    int lane = gid & 31;
    if (n >= N_NODES) return;
    int g = __ldg(&batch[n]);
    float4 v = *reinterpret_cast<const float4*>(h + (size_t)n * FC + lane * 4);
    float* o = g_psum + g * FC + lane * 4;
    atomicAdd(o + 0, v.x);
    atomicAdd(o + 1, v.y);
    atomicAdd(o + 2, v.z);
    atomicAdd(o + 3, v.w);
    if (lane == 0) atomicAdd(&g_pcnt[g], 1);
}

// ---------------- finalize: avg + classifier (one warp per graph) ----------------
__global__ void pool_finalize_kernel(const float* __restrict__ wc, const float* __restrict__ bc,
                                     float* __restrict__ logits, float* __restrict__ avg_out) {
    int g = blockIdx.x;
    int lane = threadIdx.x;  // blockDim = 32
    float inv = 1.f / fmaxf((float)g_pcnt[g], 1.f);
    float4 v = *reinterpret_cast<const float4*>(g_psum + g * FC + lane * 4);
    v.x *= inv; v.y *= inv; v.z *= inv; v.w *= inv;
    *reinterpret_cast<float4*>(avg_out + (size_t)g * FC + lane * 4) = v;
    int c = lane * 4;
    float s0 = v.x * wc[(c + 0) * NCLS + 0] + v.y * wc[(c + 1) * NCLS + 0] +
               v.z * wc[(c + 2) * NCLS + 0] + v.w * wc[(c + 3) * NCLS + 0];
    float s1 = v.x * wc[(c + 0) * NCLS + 1] + v.y * wc[(c + 1) * NCLS + 1] +
               v.z * wc[(c + 2) * NCLS + 1] + v.w * wc[(c + 3) * NCLS + 1];
#pragma unroll
    for (int o = 16; o > 0; o >>= 1) {
        s0 += __shfl_xor_sync(0xffffffffu, s0, o);
        s1 += __shfl_xor_sync(0xffffffffu, s1, o);
    }
    if (lane == 0) {
        logits[g * NCLS + 0] = s0 + bc[0];
        logits[g * NCLS + 1] = s1 + bc[1];
    }
}

// ---------------- launch ----------------
extern "C" void kernel_launch(void* const* d_in, const int* in_sizes, int n_in,
                              void* d_out, int out_size) {
    const float* x     = (const float*)d_in[0];
    const int*   ei    = (const int*)d_in[1];
    const int*   batch = (const int*)d_in[2];
    const float* w1l = (const float*)d_in[3];
    const float* w1r = (const float*)d_in[4];
    const float* b1  = (const float*)d_in[5];
    const float* g1  = (const float*)d_in[6];
    const float* be1 = (const float*)d_in[7];
    const float* w2l = (const float*)d_in[8];
    const float* w2r = (const float*)d_in[9];
    const float* b2  = (const float*)d_in[10];
    const float* g2  = (const float*)d_in[11];
    const float* be2 = (const float*)d_in[12];
    const float* w3l = (const float*)d_in[13];
    const float* w3r = (const float*)d_in[14];
    const float* b3  = (const float*)d_in[15];
    const float* g3  = (const float*)d_in[16];
    const float* be3 = (const float*)d_in[17];
    const float* wc  = (const float*)d_in[18];
    const float* bc  = (const float*)d_in[19];

    const int E = in_sizes[1] / 2;

    // output layout: (logits[512*2], h3[50000*128], avg[512*128])
    float* out    = (float*)d_out;
    float* logits = out;
    float* h3     = out + (size_t)N_GRAPHS * NCLS;
    float* avg    = h3 + (size_t)N_NODES * FC;

    float *p_h1 = nullptr, *p_h2 = nullptr;
    cudaGetSymbolAddress((void**)&p_h1, g_h1);
    cudaGetSymbolAddress((void**)&p_h2, g_h2);

    const int ZB = (N_GRAPHS * FC + 255) / 256;     // covers 65536 > 50000
    const int AGG4_BLKS = (N_NODES * FC / 4) / 256; // 6250 exactly
    const int EDGE_BLKS = (int)(((size_t)E * 32 + 255) / 256);
    const int GEMM_BLKS = (N_NODES + 63) / 64;
    const int NODE_WARP_BLKS = (int)(((size_t)N_NODES * 32 + 255) / 256);

    zero_init_kernel<<<ZB, 256>>>();
    degree_kernel<<<(E + 255) / 256, 256>>>(ei, E);
    make_inv_kernel<<<(N_NODES + 255) / 256, 256>>>();

    // layer 1
    zero_agg_kernel<<<AGG4_BLKS, 256>>>();
    scatter_kernel<<<EDGE_BLKS, 256>>>(x, ei, E);
    sage_layer_kernel<false><<<GEMM_BLKS, 256>>>(x, w1l, w1r, b1, g1, be1, p_h1);

    // layer 2 (residual)
    zero_agg_kernel<<<AGG4_BLKS, 256>>>();
    scatter_kernel<<<EDGE_BLKS, 256>>>(p_h1, ei, E);
    sage_layer_kernel<true><<<GEMM_BLKS, 256>>>(p_h1, w2l, w2r, b2, g2, be2, p_h2);

    // layer 3 (residual) -> writes h3 straight into d_out
    zero_agg_kernel<<<AGG4_BLKS, 256>>>();
    scatter_kernel<<<EDGE_BLKS, 256>>>(p_h2, ei, E);
    sage_layer_kernel<true><<<GEMM_BLKS, 256>>>(p_h2, w3l, w3r, b3, g3, be3, h3);

    // pool + classify
    pool_accum_kernel<<<NODE_WARP_BLKS, 256>>>(h3, batch);
    pool_finalize_kernel<<<N_GRAPHS, 32>>>(wc, bc, logits, avg);
}

// round 2
// speedup vs baseline: 2.1839x; 2.1839x over previous
#include <cuda_runtime.h>
#include <math.h>

#define N_NODES 50000
#define N_GRAPHS 512
#define FC 128
#define NCLS 2
#define EMAX 2000000

// ---------------- scratch (device globals; no allocs allowed) ----------------
__device__ float g_agg[(size_t)N_NODES * FC];
__device__ float g_h1[(size_t)N_NODES * FC];
__device__ float g_h2[(size_t)N_NODES * FC];
__device__ int   g_cnt[N_NODES];
__device__ int   g_off[N_NODES + 1];
__device__ int   g_cur[N_NODES];
__device__ int   g_csr[EMAX];
__device__ float g_psum[N_GRAPHS * FC];
__device__ int   g_pcnt[N_GRAPHS];

// ---------------- init ----------------
__global__ void zero_init_kernel() {
    int i = blockIdx.x * blockDim.x + threadIdx.x;
    if (i < N_NODES) g_cnt[i] = 0;
    if (i < N_GRAPHS * FC) g_psum[i] = 0.f;
    if (i < N_GRAPHS) g_pcnt[i] = 0;
}

__global__ void degree_kernel(const int* __restrict__ ei, int E) {
    int e = blockIdx.x * blockDim.x + threadIdx.x;
    if (e < E) atomicAdd(&g_cnt[ei[E + e]], 1);
}

// single-block exclusive scan over g_cnt -> g_off, g_cur
__global__ void __launch_bounds__(1024) scan_kernel() {
    __shared__ int wsum[32];
    __shared__ int s_carry;
    const int tid = threadIdx.x, lane = tid & 31, wid = tid >> 5;
    if (tid == 0) s_carry = 0;
    __syncthreads();
    for (int base = 0; base < N_NODES; base += 1024) {
        int i = base + tid;
        int orig = (i < N_NODES) ? g_cnt[i] : 0;
        int v = orig;
#pragma unroll
        for (int o = 1; o < 32; o <<= 1) {
            int t = __shfl_up_sync(0xffffffffu, v, o);
            if (lane >= o) v += t;
        }
        if (lane == 31) wsum[wid] = v;
        __syncthreads();
        if (wid == 0) {
            int s = wsum[lane];
            int so = s;
#pragma unroll
            for (int o = 1; o < 32; o <<= 1) {
                int t = __shfl_up_sync(0xffffffffu, s, o);
                if (lane >= o) s += t;
            }
            wsum[lane] = s - so;  // exclusive prefix of warp sums
        }
        __syncthreads();
        int incl = v + wsum[wid];
        int excl = incl - orig;
        int carry = s_carry;
        if (i < N_NODES) {
            g_off[i] = carry + excl;
            g_cur[i] = carry + excl;
        }
        __syncthreads();
        if (tid == 1023) s_carry = carry + incl;
        __syncthreads();
    }
    if (tid == 0) g_off[N_NODES] = s_carry;
}

__global__ void csr_fill_kernel(const int* __restrict__ ei, int E) {
    int e = blockIdx.x * blockDim.x + threadIdx.x;
    if (e >= E) return;
    int dst = __ldg(&ei[E + e]);
    int pos = atomicAdd(&g_cur[dst], 1);
    g_csr[pos] = __ldg(&ei[e]);
}

// ---------------- gather: agg[n] = mean over neighbors of x[src] (warp/node) ---
__global__ void __launch_bounds__(256) gather_kernel(const float* __restrict__ x) {
    int w = (blockIdx.x * blockDim.x + threadIdx.x) >> 5;
    int lane = threadIdx.x & 31;
    if (w >= N_NODES) return;
    const int beg = g_off[w];
    const int end = g_off[w + 1];
    float4 acc = make_float4(0.f, 0.f, 0.f, 0.f);
    for (int base = beg; base < end; base += 32) {
        int idx = base + lane;
        int si = (idx < end) ? g_csr[idx] : 0;
        int m = end - base;
        if (m >= 32) {
#pragma unroll 4
            for (int j = 0; j < 32; j++) {
                int s = __shfl_sync(0xffffffffu, si, j);
                float4 v = __ldg(reinterpret_cast<const float4*>(x + (size_t)s * FC) + lane);
                acc.x += v.x; acc.y += v.y; acc.z += v.z; acc.w += v.w;
            }
        } else {
#pragma unroll 4
            for (int j = 0; j < m; j++) {
                int s = __shfl_sync(0xffffffffu, si, j);
                float4 v = __ldg(reinterpret_cast<const float4*>(x + (size_t)s * FC) + lane);
                acc.x += v.x; acc.y += v.y; acc.z += v.z; acc.w += v.w;
            }
        }
    }
    float inv = 1.f / fmaxf((float)(end - beg), 1.f);
    acc.x *= inv; acc.y *= inv; acc.z *= inv; acc.w *= inv;
    reinterpret_cast<float4*>(g_agg + (size_t)w * FC)[lane] = acc;
}

// ---------------- fused layer: h = LN(relu(agg @ wl + bl + xin @ wr) [+ xin]) -----
template <bool RESID>
__global__ void __launch_bounds__(256) sage_layer_kernel(
    const float* __restrict__ xin,
    const float* __restrict__ wl, const float* __restrict__ wr,
    const float* __restrict__ bias, const float* __restrict__ gam,
    const float* __restrict__ bet,
    float* __restrict__ hout)
{
    __shared__ float As[64][32];    // [row][k]
    __shared__ float Bs[32][128];   // [k][n]

    const int tid  = threadIdx.x;
    const int lane = tid & 31;
    const int warp = tid >> 5;
    const int row0 = blockIdx.x * 64;

    float acc[8][4];
#pragma unroll
    for (int i = 0; i < 8; i++)
#pragma unroll
        for (int j = 0; j < 4; j++) acc[i][j] = 0.f;

    const int lr = tid >> 3;        // 0..31 (A-tile row; second row at +32)
    const int lk = (tid & 7) * 4;   // A-tile k (float4)
    const int bn = (tid & 31) * 4;  // B-tile n (float4)
    const int bk = tid >> 5;        // B-tile k base (step 8)

    for (int ph = 0; ph < 8; ph++) {
        const bool aggHalf = (ph < 4);
        const float* A = aggHalf ? g_agg : xin;
        const float* B = aggHalf ? wl : wr;
        const int kt = (ph & 3) * 32;

#pragma unroll
        for (int s = 0; s < 2; s++) {
            int r = lr + s * 32;
            int gr = row0 + r;
            float4 v = make_float4(0.f, 0.f, 0.f, 0.f);
            if (gr < N_NODES)
                v = *reinterpret_cast<const float4*>(A + (size_t)gr * FC + kt + lk);
            *reinterpret_cast<float4*>(&As[r][lk]) = v;
        }
#pragma unroll
        for (int s = 0; s < 4; s++) {
            int k = bk + s * 8;
            *reinterpret_cast<float4*>(&Bs[k][bn]) =
                *reinterpret_cast<const float4*>(B + (size_t)(kt + k) * FC + bn);
        }
        __syncthreads();

#pragma unroll
        for (int k = 0; k < 32; k++) {
            float4 b4 = *reinterpret_cast<float4*>(&Bs[k][lane * 4]);
#pragma unroll
            for (int i = 0; i < 8; i++) {
                float a = As[warp * 8 + i][k];
                acc[i][0] = fmaf(a, b4.x, acc[i][0]);
                acc[i][1] = fmaf(a, b4.y, acc[i][1]);
                acc[i][2] = fmaf(a, b4.z, acc[i][2]);
                acc[i][3] = fmaf(a, b4.w, acc[i][3]);
            }
        }
        __syncthreads();
    }

    // ---------- epilogue: bias, relu, residual, LayerNorm ----------
    const int cbase = lane * 4;
    const float4 b4  = *reinterpret_cast<const float4*>(bias + cbase);
    const float4 gm4 = *reinterpret_cast<const float4*>(gam + cbase);
    const float4 be4 = *reinterpret_cast<const float4*>(bet + cbase);

#pragma unroll
    for (int i = 0; i < 8; i++) {
        int gr = row0 + warp * 8 + i;      // warp-uniform
        if (gr >= N_NODES) continue;        // uniform branch: shuffles safe
        float v0 = fmaxf(acc[i][0] + b4.x, 0.f);
        float v1 = fmaxf(acc[i][1] + b4.y, 0.f);
        float v2 = fmaxf(acc[i][2] + b4.z, 0.f);
        float v3 = fmaxf(acc[i][3] + b4.w, 0.f);
        if (RESID) {
            float4 r4 = *reinterpret_cast<const float4*>(xin + (size_t)gr * FC + cbase);
            v0 += r4.x; v1 += r4.y; v2 += r4.z; v3 += r4.w;
        }
        float s = v0 + v1 + v2 + v3;
        float q = v0 * v0 + v1 * v1 + v2 * v2 + v3 * v3;
#pragma unroll
        for (int o = 16; o > 0; o >>= 1) {
            s += __shfl_xor_sync(0xffffffffu, s, o);
            q += __shfl_xor_sync(0xffffffffu, q, o);
        }
        float mean = s * (1.f / 128.f);
        float var  = q * (1.f / 128.f) - mean * mean;
        float rs   = rsqrtf(var + 1e-5f);
        float4 o4;
        o4.x = (v0 - mean) * rs * gm4.x + be4.x;
        o4.y = (v1 - mean) * rs * gm4.y + be4.y;
        o4.z = (v2 - mean) * rs * gm4.z + be4.z;
        o4.w = (v3 - mean) * rs * gm4.w + be4.w;
        *reinterpret_cast<float4*>(hout + (size_t)gr * FC + cbase) = o4;
    }
}

// ---------------- global mean pool accumulate (one warp per node) ----------------
__global__ void pool_accum_kernel(const float* __restrict__ h, const int* __restrict__ batch) {
    int gid = blockIdx.x * blockDim.x + threadIdx.x;
    int n = gid >> 5;
    int lane = gid & 31;
    if (n >= N_NODES) return;
    int g = __ldg(&batch[n]);
    float4 v = *reinterpret_cast<const float4*>(h + (size_t)n * FC + lane * 4);
    float* o = g_psum + g * FC + lane * 4;
    atomicAdd(o + 0, v.x);
    atomicAdd(o + 1, v.y);
    atomicAdd(o + 2, v.z);
    atomicAdd(o + 3, v.w);
    if (lane == 0) atomicAdd(&g_pcnt[g], 1);
}

// ---------------- finalize: avg + classifier (one warp per graph) ----------------
__global__ void pool_finalize_kernel(const float* __restrict__ wc, const float* __restrict__ bc,
                                     float* __restrict__ logits, float* __restrict__ avg_out) {
    int g = blockIdx.x;
    int lane = threadIdx.x;  // blockDim = 32
    float inv = 1.f / fmaxf((float)g_pcnt[g], 1.f);
    float4 v = *reinterpret_cast<const float4*>(g_psum + g * FC + lane * 4);
    v.x *= inv; v.y *= inv; v.z *= inv; v.w *= inv;
    *reinterpret_cast<float4*>(avg_out + (size_t)g * FC + lane * 4) = v;
    int c = lane * 4;
    float s0 = v.x * wc[(c + 0) * NCLS + 0] + v.y * wc[(c + 1) * NCLS + 0] +
               v.z * wc[(c + 2) * NCLS + 0] + v.w * wc[(c + 3) * NCLS + 0];
    float s1 = v.x * wc[(c + 0) * NCLS + 1] + v.y * wc[(c + 1) * NCLS + 1] +
               v.z * wc[(c + 2) * NCLS + 1] + v.w * wc[(c + 3) * NCLS + 1];
#pragma unroll
    for (int o = 16; o > 0; o >>= 1) {
        s0 += __shfl_xor_sync(0xffffffffu, s0, o);
        s1 += __shfl_xor_sync(0xffffffffu, s1, o);
    }
    if (lane == 0) {
        logits[g * NCLS + 0] = s0 + bc[0];
        logits[g * NCLS + 1] = s1 + bc[1];
    }
}

// ---------------- launch ----------------
extern "C" void kernel_launch(void* const* d_in, const int* in_sizes, int n_in,
                              void* d_out, int out_size) {
    const float* x     = (const float*)d_in[0];
    const int*   ei    = (const int*)d_in[1];
    const int*   batch = (const int*)d_in[2];
    const float* w1l = (const float*)d_in[3];
    const float* w1r = (const float*)d_in[4];
    const float* b1  = (const float*)d_in[5];
    const float* g1  = (const float*)d_in[6];
    const float* be1 = (const float*)d_in[7];
    const float* w2l = (const float*)d_in[8];
    const float* w2r = (const float*)d_in[9];
    const float* b2  = (const float*)d_in[10];
    const float* g2  = (const float*)d_in[11];
    const float* be2 = (const float*)d_in[12];
    const float* w3l = (const float*)d_in[13];
    const float* w3r = (const float*)d_in[14];
    const float* b3  = (const float*)d_in[15];
    const float* g3  = (const float*)d_in[16];
    const float* be3 = (const float*)d_in[17];
    const float* wc  = (const float*)d_in[18];
    const float* bc  = (const float*)d_in[19];

    const int E = in_sizes[1] / 2;

    // output layout: (logits[512*2], h3[50000*128], avg[512*128])
    float* out    = (float*)d_out;
    float* logits = out;
    float* h3     = out + (size_t)N_GRAPHS * NCLS;
    float* avg    = h3 + (size_t)N_NODES * FC;

    float *p_h1 = nullptr, *p_h2 = nullptr;
    cudaGetSymbolAddress((void**)&p_h1, g_h1);
    cudaGetSymbolAddress((void**)&p_h2, g_h2);

    const int ZB = (N_GRAPHS * FC + 255) / 256;
    const int GEMM_BLKS = (N_NODES + 63) / 64;
    const int NODE_WARP_BLKS = (int)(((size_t)N_NODES * 32 + 255) / 256);
    const int EDGE_BLKS = (E + 255) / 256;

    // CSR build (once; shared by all 3 layers)
    zero_init_kernel<<<ZB, 256>>>();
    degree_kernel<<<EDGE_BLKS, 256>>>(ei, E);
    scan_kernel<<<1, 1024>>>();
    csr_fill_kernel<<<EDGE_BLKS, 256>>>(ei, E);

    // layer 1
    gather_kernel<<<NODE_WARP_BLKS, 256>>>(x);
    sage_layer_kernel<false><<<GEMM_BLKS, 256>>>(x, w1l, w1r, b1, g1, be1, p_h1);

    // layer 2 (residual)
    gather_kernel<<<NODE_WARP_BLKS, 256>>>(p_h1);
    sage_layer_kernel<true><<<GEMM_BLKS, 256>>>(p_h1, w2l, w2r, b2, g2, be2, p_h2);

    // layer 3 (residual) -> writes h3 straight into d_out
    gather_kernel<<<NODE_WARP_BLKS, 256>>>(p_h2);
    sage_layer_kernel<true><<<GEMM_BLKS, 256>>>(p_h2, w3l, w3r, b3, g3, be3, h3);

    // pool + classify
    pool_accum_kernel<<<NODE_WARP_BLKS, 256>>>(h3, batch);
    pool_finalize_kernel<<<N_GRAPHS, 32>>>(wc, bc, logits, avg);
}

// round 4
// speedup vs baseline: 3.0078x; 1.3773x over previous
#include <cuda_runtime.h>
#include <cuda_bf16.h>
#include <math.h>
#include <stdint.h>

#define N_NODES 50000
#define N_GRAPHS 512
#define FC 128
#define NCLS 2
#define EMAX 2000000

// ---------------- scratch (device globals; no allocs allowed) ----------------
__device__ float g_agg[(size_t)N_NODES * FC];
__device__ float g_h1[(size_t)N_NODES * FC];
__device__ float g_h2[(size_t)N_NODES * FC];
__device__ int   g_cnt[N_NODES];
__device__ int   g_off[N_NODES + 1];
__device__ int   g_cur[N_NODES];
__device__ int   g_csr[EMAX];
__device__ float g_psum[N_GRAPHS * FC];
__device__ int   g_pcnt[N_GRAPHS];
// pre-transposed, hi/lo-split, pre-swizzled weights: [4 chunks][8192 bf16]
__device__ __nv_bfloat16 g_bt_hi[4 * 8192];
__device__ __nv_bfloat16 g_bt_lo[4 * 8192];

#define SWZ128(b) ((b) ^ (((b) >> 3) & 0x70))

__device__ __forceinline__ uint32_t smem_to_u32(const void* p) {
    uint32_t a;
    asm("{ .reg .u64 t; cvta.to.shared.u64 t, %1; cvt.u32.u64 %0, t; }" : "=r"(a) : "l"(p));
    return a;
}
__device__ __forceinline__ void ldsm4(uint32_t& r0, uint32_t& r1, uint32_t& r2, uint32_t& r3,
                                      uint32_t addr) {
    asm volatile("ldmatrix.sync.aligned.m8n8.x4.shared.b16 {%0,%1,%2,%3}, [%4];"
                 : "=r"(r0), "=r"(r1), "=r"(r2), "=r"(r3) : "r"(addr));
}
__device__ __forceinline__ void mma16816(float* d, const uint32_t* a, uint32_t b0, uint32_t b1) {
    asm volatile(
        "mma.sync.aligned.m16n8k16.row.col.f32.bf16.bf16.f32 "
        "{%0,%1,%2,%3}, {%4,%5,%6,%7}, {%8,%9}, {%0,%1,%2,%3};"
        : "+f"(d[0]), "+f"(d[1]), "+f"(d[2]), "+f"(d[3])
        : "r"(a[0]), "r"(a[1]), "r"(a[2]), "r"(a[3]), "r"(b0), "r"(b1));
}

// ---------------- init ----------------
__global__ void zero_init_kernel() {
    int i = blockIdx.x * blockDim.x + threadIdx.x;
    if (i < N_NODES) g_cnt[i] = 0;
    if (i < N_GRAPHS * FC) g_psum[i] = 0.f;
    if (i < N_GRAPHS) g_pcnt[i] = 0;
}

__global__ void degree_kernel(const int* __restrict__ ei, int E) {
    int e = blockIdx.x * blockDim.x + threadIdx.x;
    if (e < E) atomicAdd(&g_cnt[ei[E + e]], 1);
}

__global__ void __launch_bounds__(1024) scan_kernel() {
    __shared__ int wsum[32];
    __shared__ int s_carry;
    const int tid = threadIdx.x, lane = tid & 31, wid = tid >> 5;
    if (tid == 0) s_carry = 0;
    __syncthreads();
    for (int base = 0; base < N_NODES; base += 1024) {
        int i = base + tid;
        int orig = (i < N_NODES) ? g_cnt[i] : 0;
        int v = orig;
#pragma unroll
        for (int o = 1; o < 32; o <<= 1) {
            int t = __shfl_up_sync(0xffffffffu, v, o);
            if (lane >= o) v += t;
        }
        if (lane == 31) wsum[wid] = v;
        __syncthreads();
        if (wid == 0) {
            int s = wsum[lane];
            int so = s;
#pragma unroll
            for (int o = 1; o < 32; o <<= 1) {
                int t = __shfl_up_sync(0xffffffffu, s, o);
                if (lane >= o) s += t;
            }
            wsum[lane] = s - so;
        }
        __syncthreads();
        int incl = v + wsum[wid];
        int excl = incl - orig;
        int carry = s_carry;
        if (i < N_NODES) {
            g_off[i] = carry + excl;
            g_cur[i] = carry + excl;
        }
        __syncthreads();
        if (tid == 1023) s_carry = carry + incl;
        __syncthreads();
    }
    if (tid == 0) g_off[N_NODES] = s_carry;
}

__global__ void csr_fill_kernel(const int* __restrict__ ei, int E) {
    int e = blockIdx.x * blockDim.x + threadIdx.x;
    if (e >= E) return;
    int dst = __ldg(&ei[E + e]);
    int pos = atomicAdd(&g_cur[dst], 1);
    g_csr[pos] = __ldg(&ei[e]);
}

// ---------------- gather: agg[n] = mean over neighbors of x[src] (warp/node) ---
__global__ void __launch_bounds__(256) gather_kernel(const float* __restrict__ x) {
    int w = (blockIdx.x * blockDim.x + threadIdx.x) >> 5;
    int lane = threadIdx.x & 31;
    if (w >= N_NODES) return;
    const int beg = g_off[w];
    const int end = g_off[w + 1];
    float4 acc = make_float4(0.f, 0.f, 0.f, 0.f);
    for (int base = beg; base < end; base += 32) {
        int idx = base + lane;
        int si = (idx < end) ? g_csr[idx] : 0;
        int m = end - base;
        if (m >= 32) {
#pragma unroll 4
            for (int j = 0; j < 32; j++) {
                int s = __shfl_sync(0xffffffffu, si, j);
                float4 v = __ldg(reinterpret_cast<const float4*>(x + (size_t)s * FC) + lane);
                acc.x += v.x; acc.y += v.y; acc.z += v.z; acc.w += v.w;
            }
        } else {
#pragma unroll 4
            for (int j = 0; j < m; j++) {
                int s = __shfl_sync(0xffffffffu, si, j);
                float4 v = __ldg(reinterpret_cast<const float4*>(x + (size_t)s * FC) + lane);
                acc.x += v.x; acc.y += v.y; acc.z += v.z; acc.w += v.w;
            }
        }
    }
    float inv = 1.f / fmaxf((float)(end - beg), 1.f);
    acc.x *= inv; acc.y *= inv; acc.z *= inv; acc.w *= inv;
    reinterpret_cast<float4*>(g_agg + (size_t)w * FC)[lane] = acc;
}

// ---------------- weight prep: transpose + hi/lo split + pre-swizzle -----------
// B stored [n][k] (n=128 rows of 128 bytes), k in [0,256): k<128 -> wl[k][n],
// else wr[k-128][n]. Chunked by k/64; each chunk is a SW128 SMEM image.
__global__ void prep_weights_kernel(const float* __restrict__ wl, const float* __restrict__ wr) {
    int idx = blockIdx.x * blockDim.x + threadIdx.x;  // 32768
    int n = idx >> 8, k = idx & 255;
    float w = (k < 128) ? wl[k * FC + n] : wr[(k - 128) * FC + n];
    __nv_bfloat16 h = __float2bfloat16(w);
    __nv_bfloat16 l = __float2bfloat16(w - __bfloat162float(h));
    int chunk = k >> 6, kk = k & 63;
    int byte = n * 128 + kk * 2;
    int swz = SWZ128(byte);
    g_bt_hi[chunk * 8192 + (swz >> 1)] = h;
    g_bt_lo[chunk * 8192 + (swz >> 1)] = l;
}

// ---------------- tensor-core fused layer (mma.sync bf16, split hi/lo) --------
// D[128x128] = [agg|xin](128x256) @ B^T, passes hi*hi + hi*lo + lo*hi.
// 8 warps: warp (wm = wid&3) rows wm*32..+31, (wn = wid>>2) cols wn*64..+63.
#define SM_AHI 0
#define SM_ALO 16384
#define SM_BHI 32768
#define SM_BLO 49152
#define SM_PS  65536
#define SM_PQ  (SM_PS + 1024)
#define SM_TOTAL (SM_PQ + 1024)

template <bool RESID>
__global__ void __launch_bounds__(256) sage_mma_kernel(
    const float* __restrict__ xin,
    const float* __restrict__ bias, const float* __restrict__ gam,
    const float* __restrict__ bet,
    float* __restrict__ hout)
{
    extern __shared__ char smem[];
    const uint32_t sb = smem_to_u32(smem);
    const int tid = threadIdx.x;
    const int lane = tid & 31;
    const int wid = tid >> 5;
    const int wm = wid & 3;
    const int wn = wid >> 2;
    const int row0 = blockIdx.x * 128;

    float d[2][8][4];
#pragma unroll
    for (int i = 0; i < 2; i++)
#pragma unroll
        for (int j = 0; j < 8; j++)
#pragma unroll
            for (int t = 0; t < 4; t++) d[i][j][t] = 0.f;

    // per-lane ldmatrix base rows (pre-swizzle byte row offsets)
    const int lm = lane >> 3, lr = lane & 7;
    // A: m = lm: (m&1)->row block of 8, (m>>1)->k block of 16B
    int a_rowb[2];
#pragma unroll
    for (int mi = 0; mi < 2; mi++)
        a_rowb[mi] = (wm * 32 + mi * 16 + (lm & 1) * 8 + lr) * 128 + (lm >> 1) * 16;
    // B: (m>>1)->n block of 8, (m&1)->k block of 16B
    int b_rowb[4];
#pragma unroll
    for (int np = 0; np < 4; np++)
        b_rowb[np] = (wn * 64 + np * 16 + (lm >> 1) * 8 + lr) * 128 + (lm & 1) * 16;

    for (int chunk = 0; chunk < 4; chunk++) {
        const float* srcbase = (chunk < 2) ? g_agg : xin;
        const int kofs = (chunk & 1) * 64;
        // ---- build A chunk in SMEM: 128 rows x 64 fp32 -> bf16 hi/lo, SW128 ----
#pragma unroll
        for (int it = 0; it < 4; it++) {
            int idx = it * 256 + tid;       // 0..1023
            int r = idx >> 3;
            int kk0 = (idx & 7) * 8;
            int gr = row0 + r;
            float4 fa = make_float4(0.f, 0.f, 0.f, 0.f), fb = fa;
            if (gr < N_NODES) {
                const float4* p = reinterpret_cast<const float4*>(
                    srcbase + (size_t)gr * FC + kofs + kk0);
                fa = p[0]; fb = p[1];
            }
            float v[8] = {fa.x, fa.y, fa.z, fa.w, fb.x, fb.y, fb.z, fb.w};
            __nv_bfloat162 hh[4], ll[4];
#pragma unroll
            for (int j = 0; j < 4; j++) {
                __nv_bfloat16 h0 = __float2bfloat16(v[2 * j]);
                __nv_bfloat16 h1 = __float2bfloat16(v[2 * j + 1]);
                __nv_bfloat16 l0 = __float2bfloat16(v[2 * j] - __bfloat162float(h0));
                __nv_bfloat16 l1 = __float2bfloat16(v[2 * j + 1] - __bfloat162float(h1));
                hh[j] = __nv_bfloat162(h0, h1);
                ll[j] = __nv_bfloat162(l0, l1);
            }
            int swz = SWZ128(r * 128 + kk0 * 2);
            *reinterpret_cast<uint4*>(smem + SM_AHI + swz) = *reinterpret_cast<uint4*>(hh);
            *reinterpret_cast<uint4*>(smem + SM_ALO + swz) = *reinterpret_cast<uint4*>(ll);
        }
        // ---- copy pre-swizzled B chunk ----
        {
            const uint4* bh = reinterpret_cast<const uint4*>(g_bt_hi + chunk * 8192);
            const uint4* bl = reinterpret_cast<const uint4*>(g_bt_lo + chunk * 8192);
            uint4* dh = reinterpret_cast<uint4*>(smem + SM_BHI);
            uint4* dl = reinterpret_cast<uint4*>(smem + SM_BLO);
#pragma unroll
            for (int it = 0; it < 4; it++) {
                int i = it * 256 + tid;
                dh[i] = __ldg(bh + i);
                dl[i] = __ldg(bl + i);
            }
        }
        __syncthreads();

        // ---- 4 k16 steps ----
#pragma unroll
        for (int ks = 0; ks < 4; ks++) {
            uint32_t ah[2][4], al[2][4];
#pragma unroll
            for (int mi = 0; mi < 2; mi++) {
                uint32_t off = SWZ128(a_rowb[mi] + ks * 32);
                ldsm4(ah[mi][0], ah[mi][1], ah[mi][2], ah[mi][3], sb + SM_AHI + off);
                ldsm4(al[mi][0], al[mi][1], al[mi][2], al[mi][3], sb + SM_ALO + off);
            }
#pragma unroll
            for (int np = 0; np < 4; np++) {
                uint32_t off = SWZ128(b_rowb[np] + ks * 32);
                uint32_t bh0, bh1, bh2, bh3, bl0, bl1, bl2, bl3;
                ldsm4(bh0, bh1, bh2, bh3, sb + SM_BHI + off);
                ldsm4(bl0, bl1, bl2, bl3, sb + SM_BLO + off);
#pragma unroll
                for (int mi = 0; mi < 2; mi++) {
                    mma16816(d[mi][np * 2 + 0], ah[mi], bh0, bh1);
                    mma16816(d[mi][np * 2 + 0], ah[mi], bl0, bl1);
                    mma16816(d[mi][np * 2 + 0], al[mi], bh0, bh1);
                    mma16816(d[mi][np * 2 + 1], ah[mi], bh2, bh3);
                    mma16816(d[mi][np * 2 + 1], ah[mi], bl2, bl3);
                    mma16816(d[mi][np * 2 + 1], al[mi], bh2, bh3);
                }
            }
        }
        __syncthreads();
    }

    // ---------- epilogue: bias, relu, residual, LayerNorm ----------
    // thread owns rows: wm*32 + mi*16 + z*8 + (lane>>2); cols: wn*64+ni*8+(lane&3)*2
    const int cb = wn * 64 + (lane & 3) * 2;
    float2 bb[8];
#pragma unroll
    for (int ni = 0; ni < 8; ni++)
        bb[ni] = __ldg(reinterpret_cast<const float2*>(bias + cb + ni * 8));

    float s[2][2] = {{0.f, 0.f}, {0.f, 0.f}};
    float q[2][2] = {{0.f, 0.f}, {0.f, 0.f}};
#pragma unroll
    for (int mi = 0; mi < 2; mi++) {
#pragma unroll
        for (int z = 0; z < 2; z++) {
            int rl = wm * 32 + mi * 16 + z * 8 + (lane >> 2);
            int gr = row0 + rl;
            bool valid = gr < N_NODES;
#pragma unroll
            for (int ni = 0; ni < 8; ni++) {
                float2 rv = make_float2(0.f, 0.f);
                if (RESID && valid)
                    rv = *reinterpret_cast<const float2*>(xin + (size_t)gr * FC + cb + ni * 8);
                float v0 = fmaxf(d[mi][ni][z * 2 + 0] + bb[ni].x, 0.f) + rv.x;
                float v1 = fmaxf(d[mi][ni][z * 2 + 1] + bb[ni].y, 0.f) + rv.y;
                s[mi][z] += v0 + v1;
                q[mi][z] += v0 * v0 + v1 * v1;
                d[mi][ni][z * 2 + 0] = v0;
                d[mi][ni][z * 2 + 1] = v1;
            }
        }
    }
    float* ps = reinterpret_cast<float*>(smem + SM_PS);
    float* pq = reinterpret_cast<float*>(smem + SM_PQ);
#pragma unroll
    for (int mi = 0; mi < 2; mi++) {
#pragma unroll
        for (int z = 0; z < 2; z++) {
            float ss = s[mi][z], qq = q[mi][z];
            ss += __shfl_xor_sync(0xffffffffu, ss, 1);
            ss += __shfl_xor_sync(0xffffffffu, ss, 2);
            qq += __shfl_xor_sync(0xffffffffu, qq, 1);
            qq += __shfl_xor_sync(0xffffffffu, qq, 2);
            if ((lane & 3) == 0) {
                int rl = wm * 32 + mi * 16 + z * 8 + (lane >> 2);
                ps[wn * 128 + rl] = ss;
                pq[wn * 128 + rl] = qq;
            }
        }
    }
    __syncthreads();
#pragma unroll
    for (int mi = 0; mi < 2; mi++) {
#pragma unroll
        for (int z = 0; z < 2; z++) {
            int rl = wm * 32 + mi * 16 + z * 8 + (lane >> 2);
            int gr = row0 + rl;
            if (gr >= N_NODES) continue;
            float S = ps[rl] + ps[128 + rl];
            float Q = pq[rl] + pq[128 + rl];
            float mean = S * (1.f / 128.f);
            float var = Q * (1.f / 128.f) - mean * mean;
            float rs = rsqrtf(var + 1e-5f);
#pragma unroll
            for (int ni = 0; ni < 8; ni++) {
                float2 g2 = __ldg(reinterpret_cast<const float2*>(gam + cb + ni * 8));
                float2 e2 = __ldg(reinterpret_cast<const float2*>(bet + cb + ni * 8));
                float2 o2;
                o2.x = (d[mi][ni][z * 2 + 0] - mean) * rs * g2.x + e2.x;
                o2.y = (d[mi][ni][z * 2 + 1] - mean) * rs * g2.y + e2.y;
                *reinterpret_cast<float2*>(hout + (size_t)gr * FC + cb + ni * 8) = o2;
            }
        }
    }
}

// ---------------- global mean pool accumulate (one warp per node) ----------------
__global__ void pool_accum_kernel(const float* __restrict__ h, const int* __restrict__ batch) {
    int gid = blockIdx.x * blockDim.x + threadIdx.x;
    int n = gid >> 5;
    int lane = gid & 31;
    if (n >= N_NODES) return;
    int g = __ldg(&batch[n]);
    float4 v = *reinterpret_cast<const float4*>(h + (size_t)n * FC + lane * 4);
    float* o = g_psum + g * FC + lane * 4;
    atomicAdd(o + 0, v.x);
    atomicAdd(o + 1, v.y);
    atomicAdd(o + 2, v.z);
    atomicAdd(o + 3, v.w);
    if (lane == 0) atomicAdd(&g_pcnt[g], 1);
}

// ---------------- finalize: avg + classifier (one warp per graph) ----------------
__global__ void pool_finalize_kernel(const float* __restrict__ wc, const float* __restrict__ bc,
                                     float* __restrict__ logits, float* __restrict__ avg_out) {
    int g = blockIdx.x;
    int lane = threadIdx.x;  // blockDim = 32
    float inv = 1.f / fmaxf((float)g_pcnt[g], 1.f);
    float4 v = *reinterpret_cast<const float4*>(g_psum + g * FC + lane * 4);
    v.x *= inv; v.y *= inv; v.z *= inv; v.w *= inv;
    *reinterpret_cast<float4*>(avg_out + (size_t)g * FC + lane * 4) = v;
    int c = lane * 4;
    float s0 = v.x * wc[(c + 0) * NCLS + 0] + v.y * wc[(c + 1) * NCLS + 0] +
               v.z * wc[(c + 2) * NCLS + 0] + v.w * wc[(c + 3) * NCLS + 0];
    float s1 = v.x * wc[(c + 0) * NCLS + 1] + v.y * wc[(c + 1) * NCLS + 1] +
               v.z * wc[(c + 2) * NCLS + 1] + v.w * wc[(c + 3) * NCLS + 1];
#pragma unroll
    for (int o = 16; o > 0; o >>= 1) {
        s0 += __shfl_xor_sync(0xffffffffu, s0, o);
        s1 += __shfl_xor_sync(0xffffffffu, s1, o);
    }
    if (lane == 0) {
        logits[g * NCLS + 0] = s0 + bc[0];
        logits[g * NCLS + 1] = s1 + bc[1];
    }
}

// ---------------- launch ----------------
extern "C" void kernel_launch(void* const* d_in, const int* in_sizes, int n_in,
                              void* d_out, int out_size) {
    const float* x     = (const float*)d_in[0];
    const int*   ei    = (const int*)d_in[1];
    const int*   batch = (const int*)d_in[2];
    const float* w1l = (const float*)d_in[3];
    const float* w1r = (const float*)d_in[4];
    const float* b1  = (const float*)d_in[5];
    const float* g1  = (const float*)d_in[6];
    const float* be1 = (const float*)d_in[7];
    const float* w2l = (const float*)d_in[8];
    const float* w2r = (const float*)d_in[9];
    const float* b2  = (const float*)d_in[10];
    const float* g2  = (const float*)d_in[11];
    const float* be2 = (const float*)d_in[12];
    const float* w3l = (const float*)d_in[13];
    const float* w3r = (const float*)d_in[14];
    const float* b3  = (const float*)d_in[15];
    const float* g3  = (const float*)d_in[16];
    const float* be3 = (const float*)d_in[17];
    const float* wc  = (const float*)d_in[18];
    const float* bc  = (const float*)d_in[19];

    const int E = in_sizes[1] / 2;

    float* out    = (float*)d_out;
    float* logits = out;
    float* h3     = out + (size_t)N_GRAPHS * NCLS;
    float* avg    = h3 + (size_t)N_NODES * FC;

    float *p_h1 = nullptr, *p_h2 = nullptr;
    cudaGetSymbolAddress((void**)&p_h1, g_h1);
    cudaGetSymbolAddress((void**)&p_h2, g_h2);

    cudaFuncSetAttribute(sage_mma_kernel<false>,
                         cudaFuncAttributeMaxDynamicSharedMemorySize, SM_TOTAL);
    cudaFuncSetAttribute(sage_mma_kernel<true>,
                         cudaFuncAttributeMaxDynamicSharedMemorySize, SM_TOTAL);

    const int ZB = (N_GRAPHS * FC + 255) / 256;
    const int TC_BLKS = (N_NODES + 127) / 128;  // 391
    const int NODE_WARP_BLKS = (int)(((size_t)N_NODES * 32 + 255) / 256);
    const int EDGE_BLKS = (E + 255) / 256;

    // CSR build (once; shared by all 3 layers)
    zero_init_kernel<<<ZB, 256>>>();
    degree_kernel<<<EDGE_BLKS, 256>>>(ei, E);
    scan_kernel<<<1, 1024>>>();
    csr_fill_kernel<<<EDGE_BLKS, 256>>>(ei, E);

    // layer 1
    prep_weights_kernel<<<128, 256>>>(w1l, w1r);
    gather_kernel<<<NODE_WARP_BLKS, 256>>>(x);
    sage_mma_kernel<false><<<TC_BLKS, 256, SM_TOTAL>>>(x, b1, g1, be1, p_h1);

    // layer 2 (residual)
    prep_weights_kernel<<<128, 256>>>(w2l, w2r);
    gather_kernel<<<NODE_WARP_BLKS, 256>>>(p_h1);
    sage_mma_kernel<true><<<TC_BLKS, 256, SM_TOTAL>>>(p_h1, b2, g2, be2, p_h2);

    // layer 3 (residual) -> h3 straight into d_out
    prep_weights_kernel<<<128, 256>>>(w3l, w3r);
    gather_kernel<<<NODE_WARP_BLKS, 256>>>(p_h2);
    sage_mma_kernel<true><<<TC_BLKS, 256, SM_TOTAL>>>(p_h2, b3, g3, be3, h3);

    // pool + classify
    pool_accum_kernel<<<NODE_WARP_BLKS, 256>>>(h3, batch);
    pool_finalize_kernel<<<N_GRAPHS, 32>>>(wc, bc, logits, avg);
}